// round 5
// baseline (speedup 1.0000x reference)
#include <cuda_runtime.h>

#define NBLOCKS 1184
#define NTHREADS 256

__device__ double g_partials[NBLOCKS];
__device__ unsigned int g_ticket = 0;

__device__ __forceinline__ double warpReduceD(double v) {
    #pragma unroll
    for (int o = 16; o > 0; o >>= 1)
        v += __shfl_down_sync(0xffffffffu, v, o);
    return v;
}

// se3_log on (R[9] row-major, t[3]) -> xi[6] = [rho, phi]
__device__ __forceinline__ void se3_log_f(const float* R, const float* t, float* xi) {
    float tr = R[0] + R[4] + R[8];
    float c = 0.5f * (tr - 1.0f);
    c = fminf(fmaxf(c, -1.0f + 1e-7f), 1.0f - 1e-7f);
    float th = acosf(c);
    // sin(acos(c)) = sqrt(1-c^2), exact for th in [0, pi]
    float s = sqrtf(fmaxf(1.0f - c * c, 1e-20f));
    float factor = __fdividef(th, 2.0f * s);
    float px = factor * (R[7] - R[5]);
    float py = factor * (R[2] - R[6]);
    float pz = factor * (R[3] - R[1]);
    // |phi| == th analytically; clip guarantees th >= ~4.47e-4 so t2 >= 2e-7 > EPS
    float t2 = th * th;
    float D = __fdividef(1.0f, t2) - __fdividef(1.0f + c, 2.0f * th * s);
    // rho = t - 0.5*(phi x t) + D*(phi*(phi.t) - t2*t)
    float pd = px * t[0] + py * t[1] + pz * t[2];
    float cx = py * t[2] - pz * t[1];
    float cy = pz * t[0] - px * t[2];
    float cz = px * t[1] - py * t[0];
    xi[0] = t[0] - 0.5f * cx + D * (px * pd - t2 * t[0]);
    xi[1] = t[1] - 0.5f * cy + D * (py * pd - t2 * t[1]);
    xi[2] = t[2] - 0.5f * cz + D * (pz * pd - t2 * t[2]);
    xi[3] = px;
    xi[4] = py;
    xi[5] = pz;
}

__global__ void __launch_bounds__(NTHREADS)
se3_loss_main(const float* __restrict__ inp, const float* __restrict__ T,
              const float* __restrict__ P, float* __restrict__ out, int B) {
    __shared__ float sP[36];
    if (threadIdx.x < 36) sP[threadIdx.x] = P[threadIdx.x];
    __syncthreads();

    double acc = 0.0;
    for (int b = blockIdx.x * NTHREADS + threadIdx.x; b < B; b += NBLOCKS * NTHREADS) {
        // ---- load input row (6 floats, 8B-aligned) ----
        const float2* ip = (const float2*)(inp + 6 * b);
        float2 a0 = ip[0], a1 = ip[1], a2 = ip[2];
        float r0i = a0.x, r1i = a0.y, r2i = a1.x;   // rho_in
        float x = a1.y, y = a2.x, z = a2.y;         // phi_in

        // ---- se3_exp(input) ----
        float t2 = x * x + y * y + z * z;
        bool small = t2 < 1e-8f;
        float t2s = small ? 1.0f : t2;
        float th = sqrtf(t2s);
        float s, co;
        __sincosf(th, &s, &co);
        float A  = small ? 1.0f - t2 * (1.0f / 6.0f)  : __fdividef(s, th);
        float Bc = small ? 0.5f - t2 * (1.0f / 24.0f) : __fdividef(1.0f - co, t2s);
        float Cc = small ? (1.0f / 6.0f) - t2 * (1.0f / 120.0f)
                         : __fdividef(th - s, t2s * th);
        // R1 = I + A*K + Bc*(pp^T - t2*I)
        float R1[9];
        R1[0] = 1.0f + Bc * (x * x - t2);
        R1[1] = Bc * x * y - A * z;
        R1[2] = Bc * x * z + A * y;
        R1[3] = Bc * x * y + A * z;
        R1[4] = 1.0f + Bc * (y * y - t2);
        R1[5] = Bc * y * z - A * x;
        R1[6] = Bc * x * z - A * y;
        R1[7] = Bc * y * z + A * x;
        R1[8] = 1.0f + Bc * (z * z - t2);
        // t1 = Jl(phi) @ rho = rho + Bc*(phi x rho) + Cc*(phi*(phi.rho) - t2*rho)
        float pd = x * r0i + y * r1i + z * r2i;
        float cx = y * r2i - z * r1i;
        float cy = z * r0i - x * r2i;
        float cz = x * r1i - y * r0i;
        float t1[3];
        t1[0] = r0i + Bc * cx + Cc * (x * pd - t2 * r0i);
        t1[1] = r1i + Bc * cy + Cc * (y * pd - t2 * r1i);
        t1[2] = r2i + Bc * cz + Cc * (z * pd - t2 * r2i);

        // ---- load target_T_inv row (top 3 rows of 4x4) ----
        const float4* Tp = (const float4*)(T + 16 * b);
        float4 q0 = Tp[0], q1 = Tp[1], q2 = Tp[2];
        float Rt[9] = {q0.x, q0.y, q0.z, q1.x, q1.y, q1.z, q2.x, q2.y, q2.z};
        float tt[3] = {q0.w, q1.w, q2.w};

        // ---- compose: M = R1 @ Rt ; tm = R1 @ tt + t1 ----
        float M[9], tm[3];
        #pragma unroll
        for (int i = 0; i < 3; i++) {
            #pragma unroll
            for (int j = 0; j < 3; j++) {
                M[i * 3 + j] = R1[i * 3 + 0] * Rt[0 + j]
                             + R1[i * 3 + 1] * Rt[3 + j]
                             + R1[i * 3 + 2] * Rt[6 + j];
            }
            tm[i] = R1[i * 3 + 0] * tt[0] + R1[i * 3 + 1] * tt[1]
                  + R1[i * 3 + 2] * tt[2] + t1[i];
        }

        // ---- logs ----
        float xg[6], xs[6];
        se3_log_f(M, tm, xg);     // g_xi
        se3_log_f(Rt, tt, xs);    // xi_star

        // ---- quad(g) - quad(s) = (g-s)^T P (g+s)   (P symmetric) ----
        float u[6], v[6];
        #pragma unroll
        for (int i = 0; i < 6; i++) { u[i] = xg[i] - xs[i]; v[i] = xg[i] + xs[i]; }
        float q = 0.0f;
        #pragma unroll
        for (int i = 0; i < 6; i++) {
            float w = 0.0f;
            #pragma unroll
            for (int j = 0; j < 6; j++)
                w = fmaf(sP[i * 6 + j], v[j], w);
            q = fmaf(u[i], w, q);
        }
        acc += (double)q;
    }

    // ---- block reduction ----
    acc = warpReduceD(acc);
    __shared__ double sw[NTHREADS / 32];
    if ((threadIdx.x & 31) == 0) sw[threadIdx.x >> 5] = acc;
    __syncthreads();
    __shared__ bool amLast;
    if (threadIdx.x < 32) {
        double v = (threadIdx.x < NTHREADS / 32) ? sw[threadIdx.x] : 0.0;
        v = warpReduceD(v);
        if (threadIdx.x == 0) {
            g_partials[blockIdx.x] = v;
            __threadfence();
            // atomicInc wraps to 0 when old == NBLOCKS-1 -> self-resetting per replay
            unsigned int t = atomicInc(&g_ticket, NBLOCKS - 1);
            amLast = (t == NBLOCKS - 1);
        }
    }
    __syncthreads();

    // ---- last block reduces all partials (fixed order -> deterministic) ----
    if (amLast) {
        double v = 0.0;
        for (int i = threadIdx.x; i < NBLOCKS; i += NTHREADS)
            v += g_partials[i];
        v = warpReduceD(v);
        if ((threadIdx.x & 31) == 0) sw[threadIdx.x >> 5] = v;
        __syncthreads();
        if (threadIdx.x < 32) {
            double t = (threadIdx.x < NTHREADS / 32) ? sw[threadIdx.x] : 0.0;
            t = warpReduceD(t);
            if (threadIdx.x == 0)
                out[0] = (float)(0.5 / (double)B * t);
        }
    }
}

extern "C" void kernel_launch(void* const* d_in, const int* in_sizes, int n_in,
                              void* d_out, int out_size) {
    const float* inp = (const float*)d_in[0];        // (B, 6)
    const float* T   = (const float*)d_in[1];        // (B, 4, 4)
    const float* P   = (const float*)d_in[2];        // (6, 6)
    float* out = (float*)d_out;
    int B = in_sizes[0] / 6;
    se3_loss_main<<<NBLOCKS, NTHREADS>>>(inp, T, P, out, B);
}

// round 6
// speedup vs baseline: 1.3596x; 1.3596x over previous
#include <cuda_runtime.h>

#define NBLOCKS 296
#define NTHREADS 256

__device__ double g_partials[NBLOCKS];
__device__ unsigned int g_ticket = 0;

__device__ __forceinline__ double warpReduceD(double v) {
    #pragma unroll
    for (int o = 16; o > 0; o >>= 1)
        v += __shfl_down_sync(0xffffffffu, v, o);
    return v;
}

// se3_log on (R[9] row-major, t[3]) -> xi[6] = [rho, phi]
__device__ __forceinline__ void se3_log_f(const float* R, const float* t, float* xi) {
    float tr = R[0] + R[4] + R[8];
    float c = 0.5f * (tr - 1.0f);
    c = fminf(fmaxf(c, -1.0f + 1e-7f), 1.0f - 1e-7f);
    float th = acosf(c);
    // sin(acos(c)) = sqrt(1-c^2), exact for th in [0, pi]
    float s = sqrtf(fmaxf(1.0f - c * c, 1e-20f));
    float factor = __fdividef(th, 2.0f * s);
    float px = factor * (R[7] - R[5]);
    float py = factor * (R[2] - R[6]);
    float pz = factor * (R[3] - R[1]);
    float t2 = th * th;
    float D = __fdividef(1.0f, t2) - __fdividef(1.0f + c, 2.0f * th * s);
    float pd = px * t[0] + py * t[1] + pz * t[2];
    float cx = py * t[2] - pz * t[1];
    float cy = pz * t[0] - px * t[2];
    float cz = px * t[1] - py * t[0];
    xi[0] = t[0] - 0.5f * cx + D * (px * pd - t2 * t[0]);
    xi[1] = t[1] - 0.5f * cy + D * (py * pd - t2 * t[1]);
    xi[2] = t[2] - 0.5f * cz + D * (pz * pd - t2 * t[2]);
    xi[3] = px;
    xi[4] = py;
    xi[5] = pz;
}

// Full per-row loss term: returns quad(g)-quad(s) = (g-s)^T P (g+s)
__device__ __forceinline__ float row_q(float2 a0, float2 a1, float2 a2,
                                       float4 q0, float4 q1, float4 q2,
                                       const float* __restrict__ sP) {
    float r0i = a0.x, r1i = a0.y, r2i = a1.x;   // rho_in
    float x = a1.y, y = a2.x, z = a2.y;         // phi_in

    // ---- se3_exp(input) ----
    float t2 = x * x + y * y + z * z;
    bool small = t2 < 1e-8f;
    float t2s = small ? 1.0f : t2;
    float th = sqrtf(t2s);
    float s, co;
    __sincosf(th, &s, &co);
    float A  = small ? 1.0f - t2 * (1.0f / 6.0f)  : __fdividef(s, th);
    float Bc = small ? 0.5f - t2 * (1.0f / 24.0f) : __fdividef(1.0f - co, t2s);
    float Cc = small ? (1.0f / 6.0f) - t2 * (1.0f / 120.0f)
                     : __fdividef(th - s, t2s * th);
    float R1[9];
    R1[0] = 1.0f + Bc * (x * x - t2);
    R1[1] = Bc * x * y - A * z;
    R1[2] = Bc * x * z + A * y;
    R1[3] = Bc * x * y + A * z;
    R1[4] = 1.0f + Bc * (y * y - t2);
    R1[5] = Bc * y * z - A * x;
    R1[6] = Bc * x * z - A * y;
    R1[7] = Bc * y * z + A * x;
    R1[8] = 1.0f + Bc * (z * z - t2);
    float pd = x * r0i + y * r1i + z * r2i;
    float cx = y * r2i - z * r1i;
    float cy = z * r0i - x * r2i;
    float cz = x * r1i - y * r0i;
    float t1[3];
    t1[0] = r0i + Bc * cx + Cc * (x * pd - t2 * r0i);
    t1[1] = r1i + Bc * cy + Cc * (y * pd - t2 * r1i);
    t1[2] = r2i + Bc * cz + Cc * (z * pd - t2 * r2i);

    float Rt[9] = {q0.x, q0.y, q0.z, q1.x, q1.y, q1.z, q2.x, q2.y, q2.z};
    float tt[3] = {q0.w, q1.w, q2.w};

    // ---- compose: M = R1 @ Rt ; tm = R1 @ tt + t1 ----
    float M[9], tm[3];
    #pragma unroll
    for (int i = 0; i < 3; i++) {
        #pragma unroll
        for (int j = 0; j < 3; j++) {
            M[i * 3 + j] = R1[i * 3 + 0] * Rt[0 + j]
                         + R1[i * 3 + 1] * Rt[3 + j]
                         + R1[i * 3 + 2] * Rt[6 + j];
        }
        tm[i] = R1[i * 3 + 0] * tt[0] + R1[i * 3 + 1] * tt[1]
              + R1[i * 3 + 2] * tt[2] + t1[i];
    }

    float xg[6], xs[6];
    se3_log_f(M, tm, xg);     // g_xi
    se3_log_f(Rt, tt, xs);    // xi_star

    float u[6], v[6];
    #pragma unroll
    for (int i = 0; i < 6; i++) { u[i] = xg[i] - xs[i]; v[i] = xg[i] + xs[i]; }
    float q = 0.0f;
    #pragma unroll
    for (int i = 0; i < 6; i++) {
        float w = 0.0f;
        #pragma unroll
        for (int j = 0; j < 6; j++)
            w = fmaf(sP[i * 6 + j], v[j], w);
        q = fmaf(u[i], w, q);
    }
    return q;
}

__global__ void __launch_bounds__(NTHREADS, 2)
se3_loss_main(const float* __restrict__ inp, const float* __restrict__ T,
              const float* __restrict__ P, float* __restrict__ out, int B) {
    __shared__ float sP[36];
    if (threadIdx.x < 36) sP[threadIdx.x] = P[threadIdx.x];
    __syncthreads();

    const int S = NBLOCKS * NTHREADS;
    int b = blockIdx.x * NTHREADS + threadIdx.x;
    double acc = 0.0;

    // ---- main loop: two independent rows per iteration (ILP) ----
    for (; b + S < B; b += 2 * S) {
        int b1 = b + S;
        // batched front loads for both rows (max MLP)
        const float2* ipa = (const float2*)(inp + 6 * b);
        const float2* ipb = (const float2*)(inp + 6 * b1);
        const float4* Tpa = (const float4*)(T + 16 * b);
        const float4* Tpb = (const float4*)(T + 16 * b1);
        float2 a0 = ipa[0], a1 = ipa[1], a2 = ipa[2];
        float2 c0 = ipb[0], c1 = ipb[1], c2 = ipb[2];
        float4 p0 = Tpa[0], p1 = Tpa[1], p2 = Tpa[2];
        float4 r0 = Tpb[0], r1 = Tpb[1], r2 = Tpb[2];

        float qa = row_q(a0, a1, a2, p0, p1, p2, sP);
        float qb = row_q(c0, c1, c2, r0, r1, r2, sP);
        acc += (double)qa + (double)qb;
    }
    // ---- tail: at most one row left ----
    if (b < B) {
        const float2* ipa = (const float2*)(inp + 6 * b);
        const float4* Tpa = (const float4*)(T + 16 * b);
        float2 a0 = ipa[0], a1 = ipa[1], a2 = ipa[2];
        float4 p0 = Tpa[0], p1 = Tpa[1], p2 = Tpa[2];
        acc += (double)row_q(a0, a1, a2, p0, p1, p2, sP);
    }

    // ---- block reduction ----
    acc = warpReduceD(acc);
    __shared__ double sw[NTHREADS / 32];
    if ((threadIdx.x & 31) == 0) sw[threadIdx.x >> 5] = acc;
    __syncthreads();
    __shared__ bool amLast;
    if (threadIdx.x < 32) {
        double v = (threadIdx.x < NTHREADS / 32) ? sw[threadIdx.x] : 0.0;
        v = warpReduceD(v);
        if (threadIdx.x == 0) {
            g_partials[blockIdx.x] = v;
            __threadfence();
            unsigned int t = atomicInc(&g_ticket, NBLOCKS - 1);  // self-resetting
            amLast = (t == NBLOCKS - 1);
        }
    }
    __syncthreads();

    // ---- last block reduces all partials (fixed order -> deterministic) ----
    if (amLast) {
        double v = 0.0;
        for (int i = threadIdx.x; i < NBLOCKS; i += NTHREADS)
            v += g_partials[i];
        v = warpReduceD(v);
        if ((threadIdx.x & 31) == 0) sw[threadIdx.x >> 5] = v;
        __syncthreads();
        if (threadIdx.x < 32) {
            double t = (threadIdx.x < NTHREADS / 32) ? sw[threadIdx.x] : 0.0;
            t = warpReduceD(t);
            if (threadIdx.x == 0)
                out[0] = (float)(0.5 / (double)B * t);
        }
    }
}

extern "C" void kernel_launch(void* const* d_in, const int* in_sizes, int n_in,
                              void* d_out, int out_size) {
    const float* inp = (const float*)d_in[0];        // (B, 6)
    const float* T   = (const float*)d_in[1];        // (B, 4, 4)
    const float* P   = (const float*)d_in[2];        // (6, 6)
    float* out = (float*)d_out;
    int B = in_sizes[0] / 6;
    se3_loss_main<<<NBLOCKS, NTHREADS>>>(inp, T, P, out, B);
}